// round 17
// baseline (speedup 1.0000x reference)
#include <cuda_runtime.h>

#define DIMN 32
#define TPB 256

__constant__ float4 c_w4[DIMN / 4];   // w packed as 8 float4s

__device__ __forceinline__ unsigned long long pack2(float lo, float hi) {
    unsigned long long r;
    asm("mov.b64 %0, {%1, %2};" : "=l"(r) : "f"(lo), "f"(hi));
    return r;
}
__device__ __forceinline__ void unpack2(unsigned long long v, float& lo, float& hi) {
    asm("mov.b64 {%0, %1}, %2;" : "=f"(lo), "=f"(hi) : "l"(v));
}
__device__ __forceinline__ unsigned long long fma2(unsigned long long a,
                                                   unsigned long long b,
                                                   unsigned long long c) {
    unsigned long long d;
    asm("fma.rn.f32x2 %0, %1, %2, %3;" : "=l"(d) : "l"(a), "l"(b), "l"(c));
    return d;
}

__global__ __launch_bounds__(TPB, 6) void poly_cmem_v4_kernel(
    const float* __restrict__ x,
    float* __restrict__ out,
    int n_vec4)
{
    int base = blockIdx.x * (2 * TPB) + threadIdx.x;
    int i0 = base;
    int i1 = base + TPB;

    const float4* __restrict__ x4 = reinterpret_cast<const float4*>(x);
    float4* __restrict__ o4 = reinterpret_cast<float4*>(out);

    float4 xv0 = (i0 < n_vec4) ? __ldg(&x4[i0]) : make_float4(0.f, 0.f, 0.f, 0.f);
    float4 xv1 = (i1 < n_vec4) ? __ldg(&x4[i1]) : make_float4(0.f, 0.f, 0.f, 0.f);

    // 4 independent packed chains = 8 elements (named u64 scalars only).
    unsigned long long p0 = pack2(xv0.x, xv0.y);
    unsigned long long p1 = pack2(xv0.z, xv0.w);
    unsigned long long p2 = pack2(xv1.x, xv1.y);
    unsigned long long p3 = pack2(xv1.z, xv1.w);

#define STEP(WK) { \
        unsigned long long wkk = pack2(WK, WK); \
        a0 = fma2(a0, p0, wkk); \
        a1 = fma2(a1, p1, wkk); \
        a2 = fma2(a2, p2, wkk); \
        a3 = fma2(a3, p3, wkk); }

    // Group 7 holds w28..w31: w31 initializes, then steps 30,29,28.
    float4 wv = c_w4[7];
    unsigned long long a0 = pack2(wv.w, wv.w);
    unsigned long long a1 = a0, a2 = a0, a3 = a0;
    STEP(wv.z) STEP(wv.y) STEP(wv.x)

    // Groups 6..0: one LDC.128 feeds 4 Horner steps (w[4g+3] .. w[4g]).
#pragma unroll
    for (int g = 6; g >= 0; --g) {
        wv = c_w4[g];
        STEP(wv.w) STEP(wv.z) STEP(wv.y) STEP(wv.x)
    }
#undef STEP

    float4 ov;
    if (i0 < n_vec4) {
        unpack2(a0, ov.x, ov.y);
        unpack2(a1, ov.z, ov.w);
        o4[i0] = ov;
    }
    if (i1 < n_vec4) {
        unpack2(a2, ov.x, ov.y);
        unpack2(a3, ov.z, ov.w);
        o4[i1] = ov;
    }
}

extern "C" void kernel_launch(void* const* d_in, const int* in_sizes, int n_in,
                              void* d_out, int out_size) {
    const float* x = (const float*)d_in[0];
    const float* w = (const float*)d_in[1];
    float* out = (float*)d_out;

    int n = in_sizes[0];            // 4194304
    int n_vec4 = n / 4;             // 1048576 float4s
    int blocks = (n_vec4 + 2 * TPB - 1) / (2 * TPB);   // 2048

    // Graph-capturable async D2D copy into the constant bank.
    cudaMemcpyToSymbolAsync(c_w4, w, DIMN * sizeof(float), 0,
                            cudaMemcpyDeviceToDevice, 0);

    poly_cmem_v4_kernel<<<blocks, TPB>>>(x, out, n_vec4);
}